// round 12
// baseline (speedup 1.0000x reference)
#include <cuda_runtime.h>
#include <cuda_bf16.h>
#include <cstdint>

#define NB 32
#define HH 56
#define WW 56
#define CC 256
#define HW (HH*WW)           // 3136
#define M_TOTAL (NB*HW)      // 100352
#define TILES 784            // 28*28 tiles per image
#define M2 (NB*TILES)        // 25088 winograd tiles

#define BM2 64               // tiles per CTA
#define BNc 64               // couts per CTA (4 groups -> 1568 CTAs, 3.9% tail waste)
#define A_ST (BM2*512)       // 32768
#define B_ST (BNc*512)       // 32768
#define STG (A_ST+B_ST)      // 65536
#define SMEM_TOTAL (1024 + 2*STG)   // 132096

__device__ __align__(16) uint8_t       g_xq[(size_t)M_TOTAL * CC];   // int {0..3}
__device__ __align__(16) __nv_bfloat16 g_V[(size_t)16 * M2 * CC];    // [t][m2][cin] swizzled rows
__device__ __align__(16) __nv_bfloat16 g_U[(size_t)16 * CC * CC];    // [t][cout][cin] swizzled rows
__device__ unsigned int g_wmax_bits;   // idempotent across replays (same input)

// row-internal swizzle: 16B-unit u (0..31), row low bits rx
__device__ __forceinline__ uint32_t swz(uint32_t u, uint32_t rx) {
    return (u & 24u) | ((u ^ rx) & 7u);
}

// ---------------- prologue kernels ----------------
__global__ void wmax_kernel(const float* __restrict__ w) {
    int i0 = blockIdx.x * blockDim.x + threadIdx.x;
    int stride = gridDim.x * blockDim.x;
    float m = 0.f;
    for (int i = i0; i < CC * 9 * CC; i += stride)
        m = fmaxf(m, fabsf(tanhf(w[i])));
    #pragma unroll
    for (int off = 16; off > 0; off >>= 1)
        m = fmaxf(m, __shfl_xor_sync(0xffffffffu, m, off));
    if ((threadIdx.x & 31) == 0)
        atomicMax(&g_wmax_bits, __float_as_uint(m));
}

__global__ void xquant_kernel(const float* __restrict__ x) {
    int i = blockIdx.x * blockDim.x + threadIdx.x;   // over M_TOTAL*CC/4
    float4 v = reinterpret_cast<const float4*>(x)[i];
    uchar4 q;
    q.x = (unsigned char)(int)rintf(fminf(fmaxf(v.x, 0.f), 1.f) * 3.0f);
    q.y = (unsigned char)(int)rintf(fminf(fmaxf(v.y, 0.f), 1.f) * 3.0f);
    q.z = (unsigned char)(int)rintf(fminf(fmaxf(v.z, 0.f), 1.f) * 3.0f);
    q.w = (unsigned char)(int)rintf(fminf(fmaxf(v.w, 0.f), 1.f) * 3.0f);
    reinterpret_cast<uchar4*>(g_xq)[i] = q;
}

// weight transform: quantize + U = G g G^T (multiples of 1/4, exact in bf16)
__global__ void utrans_kernel(const float* __restrict__ w) {
    const int idx  = blockIdx.x * 256 + threadIdx.x;   // 65536
    const int cout = idx & 255;
    const int cin  = idx >> 8;
    const float mx = __uint_as_float(g_wmax_bits);
    float g[3][3];
    #pragma unroll
    for (int ky = 0; ky < 3; ky++)
        #pragma unroll
        for (int kx = 0; kx < 3; kx++) {
            float t  = tanhf(w[((ky * 3 + kx) * CC + cin) * CC + cout]);
            float tn = t / mx * 0.5f + 0.5f;
            float kq = rintf(tn * 3.0f);
            kq = fminf(fmaxf(kq, 0.f), 3.f);
            g[ky][kx] = 2.0f * kq - 3.0f;
        }
    float R[3][4];
    #pragma unroll
    for (int ky = 0; ky < 3; ky++) {
        R[ky][0] = g[ky][0];
        R[ky][1] = 0.5f * (g[ky][0] + g[ky][1] + g[ky][2]);
        R[ky][2] = 0.5f * (g[ky][0] - g[ky][1] + g[ky][2]);
        R[ky][3] = g[ky][2];
    }
    const uint32_t off = swz((uint32_t)cin >> 3, (uint32_t)cout & 7u) * 16
                       + ((uint32_t)cin & 7u) * 2;
    uint8_t* base = (uint8_t*)g_U + (size_t)cout * 512 + off;
    #pragma unroll
    for (int j = 0; j < 4; j++) {
        float u0 = R[0][j];
        float u1 = 0.5f * (R[0][j] + R[1][j] + R[2][j]);
        float u2 = 0.5f * (R[0][j] - R[1][j] + R[2][j]);
        float u3 = R[2][j];
        *(__nv_bfloat16*)(base + (size_t)(0 * 4 + j) * (CC * 512)) = __float2bfloat16(u0);
        *(__nv_bfloat16*)(base + (size_t)(1 * 4 + j) * (CC * 512)) = __float2bfloat16(u1);
        *(__nv_bfloat16*)(base + (size_t)(2 * 4 + j) * (CC * 512)) = __float2bfloat16(u2);
        *(__nv_bfloat16*)(base + (size_t)(3 * 4 + j) * (CC * 512)) = __float2bfloat16(u3);
    }
}

// input transform: V = B^T d B, vectorized 4 cins/thread with s16x2 SIMD.
__global__ void vtrans_kernel() {
    const int m2 = blockIdx.x * 4 + (threadIdx.x >> 6);   // 4 tiles per 256-thr block
    const int c4 = threadIdx.x & 63;                      // cins 4*c4 .. 4*c4+3
    const int n   = m2 / TILES;
    const int r   = m2 - n * TILES;
    const int th  = r / 28;
    const int tw  = r - th * 28;
    const int ih0 = 2 * th - 1, iw0 = 2 * tw - 1;
    const uint8_t* xb = g_xq + ((size_t)n * HW) * CC + c4 * 4;

    uint32_t d[4][4][2];
    #pragma unroll
    for (int a = 0; a < 4; a++) {
        const int ih = ih0 + a;
        #pragma unroll
        for (int b = 0; b < 4; b++) {
            const int iw = iw0 + b;
            const bool ok = ((unsigned)ih < HH) && ((unsigned)iw < WW);
            uint32_t v = ok ? *(const uint32_t*)(xb + (size_t)(ih * WW + iw) * CC) : 0u;
            d[a][b][0] = (v & 0xFFu) | ((v & 0xFF00u) << 8);
            d[a][b][1] = ((v >> 16) & 0xFFu) | ((v & 0xFF000000u) >> 8);
        }
    }

    const uint32_t off = swz((uint32_t)c4 >> 1, (uint32_t)m2 & 7u) * 16
                       + ((uint32_t)c4 & 1u) * 8;
    uint8_t* base = (uint8_t*)g_V + (size_t)m2 * 512 + off;
    const size_t tstride = (size_t)M2 * 512;

    #pragma unroll
    for (int j = 0; j < 4; j++) {
        uint32_t tj[4][2];
        #pragma unroll
        for (int a = 0; a < 4; a++) {
            #pragma unroll
            for (int h = 0; h < 2; h++) {
                uint32_t t;
                if (j == 0)      t = __vsub2(d[a][0][h], d[a][2][h]);
                else if (j == 1) t = __vadd2(d[a][1][h], d[a][2][h]);
                else if (j == 2) t = __vsub2(d[a][2][h], d[a][1][h]);
                else             t = __vsub2(d[a][1][h], d[a][3][h]);
                tj[a][h] = t;
            }
        }
        #pragma unroll
        for (int i = 0; i < 4; i++) {
            uint32_t vv[2];
            #pragma unroll
            for (int h = 0; h < 2; h++) {
                if (i == 0)      vv[h] = __vsub2(tj[0][h], tj[2][h]);
                else if (i == 1) vv[h] = __vadd2(tj[1][h], tj[2][h]);
                else if (i == 2) vv[h] = __vsub2(tj[2][h], tj[1][h]);
                else             vv[h] = __vsub2(tj[1][h], tj[3][h]);
            }
            float f0 = (float)(short)(vv[0] & 0xFFFFu);
            float f1 = (float)(short)(vv[0] >> 16);
            float f2 = (float)(short)(vv[1] & 0xFFFFu);
            float f3 = (float)(short)(vv[1] >> 16);
            __nv_bfloat162 p0 = __floats2bfloat162_rn(f0, f1);
            __nv_bfloat162 p1 = __floats2bfloat162_rn(f2, f3);
            uint2 pk;
            pk.x = *(uint32_t*)&p0;
            pk.y = *(uint32_t*)&p1;
            *(uint2*)(base + (size_t)(i * 4 + j) * tstride) = pk;
        }
    }
}

// ---------------- PTX helpers ----------------
__device__ __forceinline__ void ldsm_x4(uint32_t addr, int& r0, int& r1, int& r2, int& r3) {
    asm volatile("ldmatrix.sync.aligned.m8n8.x4.shared.b16 {%0,%1,%2,%3}, [%4];\n"
                 : "=r"(r0), "=r"(r1), "=r"(r2), "=r"(r3) : "r"(addr));
}
#define MMA_BF16(d, A, B)                                                           \
    asm volatile("mma.sync.aligned.m16n8k16.row.col.f32.bf16.bf16.f32 "             \
                 "{%0,%1,%2,%3}, {%4,%5,%6,%7}, {%8,%9}, {%0,%1,%2,%3};\n"          \
                 : "+f"((d)[0]), "+f"((d)[1]), "+f"((d)[2]), "+f"((d)[3])           \
                 : "r"((A)[0]), "r"((A)[1]), "r"((A)[2]), "r"((A)[3]),              \
                   "r"((B)[0]), "r"((B)[1]))

__device__ __forceinline__ void bulk_cp(uint32_t dst, const void* src, uint32_t bytes, uint32_t mbar) {
    asm volatile(
        "cp.async.bulk.shared::cluster.global.mbarrier::complete_tx::bytes [%0], [%1], %2, [%3];\n"
        :: "r"(dst), "l"(src), "r"(bytes), "r"(mbar) : "memory");
}
__device__ __forceinline__ void mbar_init(uint32_t addr, uint32_t count) {
    asm volatile("mbarrier.init.shared.b64 [%0], %1;\n" :: "r"(addr), "r"(count) : "memory");
}
__device__ __forceinline__ void mbar_expect(uint32_t addr, uint32_t bytes) {
    asm volatile("mbarrier.arrive.expect_tx.shared.b64 _, [%0], %1;\n"
                 :: "r"(addr), "r"(bytes) : "memory");
}
__device__ __forceinline__ void mbar_wait(uint32_t addr, uint32_t parity) {
    uint32_t done = 0;
    while (!done) {
        asm volatile(
            "{\n\t.reg .pred p;\n\t"
            "mbarrier.try_wait.parity.acquire.cta.shared::cta.b64 p, [%1], %2, 0x989680;\n\t"
            "selp.b32 %0, 1, 0, p;\n\t}"
            : "=r"(done) : "r"(addr), "r"(parity) : "memory");
    }
}

// ---------------- winograd GEMM (bulk-copy pipeline) + fused output transform ----------------
__global__ __launch_bounds__(512, 1) void conv_kernel(float* __restrict__ out) {
    extern __shared__ __align__(1024) int8_t smem[];
    const uint32_t sbase  = (uint32_t)__cvta_generic_to_shared(smem);
    const uint32_t sMbar  = sbase;           // 2 mbarriers
    const uint32_t sStage = sbase + 1024;

    const int tid  = threadIdx.x;
    const int lane = tid & 31;
    const int wid  = tid >> 5;
    const int bn   = blockIdx.x;       // 0..3 (cout group of 64)
    const int bm   = blockIdx.y;       // 0..391 (tile group)

    if (tid == 0) { mbar_init(sMbar, 1); mbar_init(sMbar + 8, 1); }
    __syncthreads();

    const uint8_t* Ag = (const uint8_t*)g_V + (size_t)bm * BM2 * 512;
    const uint8_t* Bg = (const uint8_t*)g_U + (size_t)bn * BNc * 512;

    auto issue = [&](int s) {
        if (tid == 0) {
            const uint32_t mb = sMbar + (s & 1) * 8;
            const uint32_t da = sStage + (s & 1) * STG;
            mbar_expect(mb, STG);
            bulk_cp(da,        Ag + (size_t)s * ((size_t)M2 * 512), A_ST, mb);
            bulk_cp(da + A_ST, Bg + (size_t)s * (CC * 512),         B_ST, mb);
        }
    };

    // ---- warp/fragment indexing: 16 warps as 4(m) x 4(n); warp tile 16x16
    const int wm  = (wid >> 2) * 16;
    const int wn  = (wid & 3) * 16;
    const int grp = lane >> 2;
    const int tig = lane & 3;

    const uint32_t rowA = wm + (lane & 15);
    const uint32_t hiA  = lane >> 4;
    const uint32_t rxA  = rowA & 7u;
    const uint32_t q    = lane >> 3;
    const uint32_t l8   = lane & 7;
    const uint32_t hiB  = q & 1;
    const uint32_t rowB = wn + (q >> 1) * 8 + l8;
    const uint32_t rxB  = rowB & 7u;

    float acc[2][4];
    float oacc[2][2][2][4];
    #pragma unroll
    for (int ni = 0; ni < 2; ni++)
        #pragma unroll
        for (int r = 0; r < 4; r++) acc[ni][r] = 0.f;
    #pragma unroll
    for (int p = 0; p < 2; p++)
        #pragma unroll
        for (int qq = 0; qq < 2; qq++)
            #pragma unroll
            for (int ni = 0; ni < 2; ni++)
                #pragma unroll
                for (int r = 0; r < 4; r++) oacc[p][qq][ni][r] = 0.f;

    auto compute = [&](int buf) {
        const uint32_t abase = sStage + buf * STG + rowA * 512;
        const uint32_t bbase = sStage + buf * STG + A_ST + rowB * 512;
        #pragma unroll
        for (int j = 0; j < 16; j++) {
            const uint32_t uA = 2 * j + hiA;
            int a[4];
            ldsm_x4(abase + swz(uA, rxA) * 16, a[0], a[1], a[2], a[3]);
            const uint32_t uB = 2 * j + hiB;
            int b[2][2];
            ldsm_x4(bbase + swz(uB, rxB) * 16, b[0][0], b[0][1], b[1][0], b[1][1]);
            #pragma unroll
            for (int ni = 0; ni < 2; ni++)
                MMA_BF16(acc[ni], a, b[ni]);
        }
    };

    auto fold = [&](int t) {
        const int i = t >> 2, j = t & 3;
        const float ci0 = (i == 3) ? 0.f : 1.f;
        const float ci1 = (i == 0) ? 0.f : ((i == 1) ? 1.f : -1.f);
        const float cj0 = (j == 3) ? 0.f : 1.f;
        const float cj1 = (j == 0) ? 0.f : ((j == 1) ? 1.f : -1.f);
        const float cp[2] = {ci0, ci1};
        const float cq[2] = {cj0, cj1};
        #pragma unroll
        for (int p = 0; p < 2; p++)
            #pragma unroll
            for (int qq = 0; qq < 2; qq++) {
                const float c = cp[p] * cq[qq];
                if (c != 0.f) {
                    #pragma unroll
                    for (int ni = 0; ni < 2; ni++)
                        #pragma unroll
                        for (int r = 0; r < 4; r++)
                            oacc[p][qq][ni][r] += c * acc[ni][r];
                }
            }
        #pragma unroll
        for (int ni = 0; ni < 2; ni++)
            #pragma unroll
            for (int r = 0; r < 4; r++) acc[ni][r] = 0.f;
    };

    // ---- double-buffered bulk pipeline over 16 t-points
    issue(0);
    issue(1);
    for (int s = 0; s < 16; s++) {
        mbar_wait(sMbar + (s & 1) * 8, (s >> 1) & 1);
        compute(s & 1);
        fold(s);
        __syncthreads();
        if (s + 2 < 16) issue(s + 2);
    }

    // ---- epilogue: write 2x2 output pixels per tile row, scaled by 1/9
    const float inv9 = 1.0f / 9.0f;
    #pragma unroll
    for (int half = 0; half < 2; half++) {
        const int mrow  = bm * BM2 + wm + grp + half * 8;
        const int n_img = mrow / TILES;
        const int rr    = mrow - n_img * TILES;
        const int th    = rr / 28;
        const int tw    = rr - th * 28;
        #pragma unroll
        for (int p = 0; p < 2; p++) {
            const int oh = 2 * th + p;
            #pragma unroll
            for (int qq = 0; qq < 2; qq++) {
                const int ow = 2 * tw + qq;
                float* orow = out + (size_t)(n_img * HW + oh * WW + ow) * CC
                            + bn * BNc + wn + tig * 2;
                #pragma unroll
                for (int ni = 0; ni < 2; ni++) {
                    float2 v;
                    v.x = oacc[p][qq][ni][half * 2 + 0] * inv9;
                    v.y = oacc[p][qq][ni][half * 2 + 1] * inv9;
                    *(float2*)&orow[ni * 8] = v;
                }
            }
        }
    }
}

// ---------------- launch ----------------
extern "C" void kernel_launch(void* const* d_in, const int* in_sizes, int n_in,
                              void* d_out, int out_size) {
    const float* x = (const float*)d_in[0];
    const float* w = (const float*)d_in[1];
    if (n_in >= 2 && in_sizes[0] == CC * 9 * CC) {
        x = (const float*)d_in[1];
        w = (const float*)d_in[0];
    }
    float* out = (float*)d_out;

    cudaFuncSetAttribute(conv_kernel, cudaFuncAttributeMaxDynamicSharedMemorySize, SMEM_TOTAL);

    wmax_kernel<<<1024, 256>>>(w);
    xquant_kernel<<<M_TOTAL * CC / 4 / 256, 256>>>(x);
    utrans_kernel<<<256, 256>>>(w);
    vtrans_kernel<<<M2 / 4, 256>>>();
    conv_kernel<<<dim3(4, M2 / BM2), 512, SMEM_TOTAL>>>(out);
}

// round 13
// speedup vs baseline: 1.1876x; 1.1876x over previous
#include <cuda_runtime.h>
#include <cuda_bf16.h>
#include <cstdint>

#define NB 32
#define HH 56
#define WW 56
#define CC 256
#define HW (HH*WW)           // 3136
#define M_TOTAL (NB*HW)      // 100352
#define TILES 784            // 28*28 tiles per image
#define M2 (NB*TILES)        // 25088 winograd tiles

#define BM2 64               // tiles per CTA
#define BNc 128              // couts per CTA (R11 proven config)
#define A_ST (BM2*512)       // 32768
#define B_ST (BNc*512)       // 65536
#define STG (A_ST+B_ST)      // 98304
#define SMEM_TOTAL (1024 + 2*STG)   // 197632

__device__ __align__(16) __nv_bfloat16 g_V[(size_t)16 * M2 * CC];    // [t][m2][cin] swizzled rows
__device__ __align__(16) __nv_bfloat16 g_U[(size_t)16 * CC * CC];    // [t][cout][cin] swizzled rows
__device__ unsigned int g_wmax_bits;   // idempotent across replays (same input)

// row-internal swizzle: 16B-unit u (0..31), row low bits rx
__device__ __forceinline__ uint32_t swz(uint32_t u, uint32_t rx) {
    return (u & 24u) | ((u ^ rx) & 7u);
}

// ---------------- prologue kernels ----------------
// max|w| only — tanh is monotonic, so tanh(max|w|) = max|tanh(w)| (applied in utrans)
__global__ void wmax_kernel(const float* __restrict__ w) {
    int i0 = blockIdx.x * blockDim.x + threadIdx.x;
    int stride = gridDim.x * blockDim.x;
    float m = 0.f;
    for (int i = i0; i < CC * 9 * CC; i += stride)
        m = fmaxf(m, fabsf(w[i]));
    #pragma unroll
    for (int off = 16; off > 0; off >>= 1)
        m = fmaxf(m, __shfl_xor_sync(0xffffffffu, m, off));
    if ((threadIdx.x & 31) == 0)
        atomicMax(&g_wmax_bits, __float_as_uint(m));
}

// weight transform: quantize + U = G g G^T (multiples of 1/4, exact in bf16)
__global__ void utrans_kernel(const float* __restrict__ w) {
    const int idx  = blockIdx.x * 256 + threadIdx.x;   // 65536
    const int cout = idx & 255;
    const int cin  = idx >> 8;
    const float mx = tanhf(__uint_as_float(g_wmax_bits));
    float g[3][3];
    #pragma unroll
    for (int ky = 0; ky < 3; ky++)
        #pragma unroll
        for (int kx = 0; kx < 3; kx++) {
            float t  = tanhf(w[((ky * 3 + kx) * CC + cin) * CC + cout]);
            float tn = t / mx * 0.5f + 0.5f;
            float kq = rintf(tn * 3.0f);
            kq = fminf(fmaxf(kq, 0.f), 3.f);
            g[ky][kx] = 2.0f * kq - 3.0f;
        }
    float R[3][4];
    #pragma unroll
    for (int ky = 0; ky < 3; ky++) {
        R[ky][0] = g[ky][0];
        R[ky][1] = 0.5f * (g[ky][0] + g[ky][1] + g[ky][2]);
        R[ky][2] = 0.5f * (g[ky][0] - g[ky][1] + g[ky][2]);
        R[ky][3] = g[ky][2];
    }
    const uint32_t off = swz((uint32_t)cin >> 3, (uint32_t)cout & 7u) * 16
                       + ((uint32_t)cin & 7u) * 2;
    uint8_t* base = (uint8_t*)g_U + (size_t)cout * 512 + off;
    #pragma unroll
    for (int j = 0; j < 4; j++) {
        float u0 = R[0][j];
        float u1 = 0.5f * (R[0][j] + R[1][j] + R[2][j]);
        float u2 = 0.5f * (R[0][j] - R[1][j] + R[2][j]);
        float u3 = R[2][j];
        *(__nv_bfloat16*)(base + (size_t)(0 * 4 + j) * (CC * 512)) = __float2bfloat16(u0);
        *(__nv_bfloat16*)(base + (size_t)(1 * 4 + j) * (CC * 512)) = __float2bfloat16(u1);
        *(__nv_bfloat16*)(base + (size_t)(2 * 4 + j) * (CC * 512)) = __float2bfloat16(u2);
        *(__nv_bfloat16*)(base + (size_t)(3 * 4 + j) * (CC * 512)) = __float2bfloat16(u3);
    }
}

// fused activation quantize + input transform: V = B^T quant(d) B
// 4 cins/thread, s16x2 SIMD transform; integers |V| <= 12, exact in bf16.
__global__ void vtrans_kernel(const float* __restrict__ x) {
    const int m2 = blockIdx.x * 4 + (threadIdx.x >> 6);   // 4 tiles per 256-thr block
    const int c4 = threadIdx.x & 63;                      // cins 4*c4 .. 4*c4+3
    const int n   = m2 / TILES;
    const int r   = m2 - n * TILES;
    const int th  = r / 28;
    const int tw  = r - th * 28;
    const int ih0 = 2 * th - 1, iw0 = 2 * tw - 1;
    const float* xb = x + ((size_t)n * HW) * CC + c4 * 4;

    uint32_t d[4][4][2];
    #pragma unroll
    for (int a = 0; a < 4; a++) {
        const int ih = ih0 + a;
        #pragma unroll
        for (int b = 0; b < 4; b++) {
            const int iw = iw0 + b;
            const bool ok = ((unsigned)ih < HH) && ((unsigned)iw < WW);
            if (ok) {
                float4 v = *(const float4*)(xb + (size_t)(ih * WW + iw) * CC);
                uint32_t q0 = (uint32_t)(int)rintf(fminf(fmaxf(v.x, 0.f), 1.f) * 3.0f);
                uint32_t q1 = (uint32_t)(int)rintf(fminf(fmaxf(v.y, 0.f), 1.f) * 3.0f);
                uint32_t q2 = (uint32_t)(int)rintf(fminf(fmaxf(v.z, 0.f), 1.f) * 3.0f);
                uint32_t q3 = (uint32_t)(int)rintf(fminf(fmaxf(v.w, 0.f), 1.f) * 3.0f);
                d[a][b][0] = q0 | (q1 << 16);
                d[a][b][1] = q2 | (q3 << 16);
            } else {
                d[a][b][0] = 0u;
                d[a][b][1] = 0u;
            }
        }
    }

    const uint32_t off = swz((uint32_t)c4 >> 1, (uint32_t)m2 & 7u) * 16
                       + ((uint32_t)c4 & 1u) * 8;
    uint8_t* base = (uint8_t*)g_V + (size_t)m2 * 512 + off;
    const size_t tstride = (size_t)M2 * 512;

    #pragma unroll
    for (int j = 0; j < 4; j++) {
        uint32_t tj[4][2];
        #pragma unroll
        for (int a = 0; a < 4; a++) {
            #pragma unroll
            for (int h = 0; h < 2; h++) {
                uint32_t t;
                if (j == 0)      t = __vsub2(d[a][0][h], d[a][2][h]);
                else if (j == 1) t = __vadd2(d[a][1][h], d[a][2][h]);
                else if (j == 2) t = __vsub2(d[a][2][h], d[a][1][h]);
                else             t = __vsub2(d[a][1][h], d[a][3][h]);
                tj[a][h] = t;
            }
        }
        #pragma unroll
        for (int i = 0; i < 4; i++) {
            uint32_t vv[2];
            #pragma unroll
            for (int h = 0; h < 2; h++) {
                if (i == 0)      vv[h] = __vsub2(tj[0][h], tj[2][h]);
                else if (i == 1) vv[h] = __vadd2(tj[1][h], tj[2][h]);
                else if (i == 2) vv[h] = __vsub2(tj[2][h], tj[1][h]);
                else             vv[h] = __vsub2(tj[1][h], tj[3][h]);
            }
            float f0 = (float)(short)(vv[0] & 0xFFFFu);
            float f1 = (float)(short)(vv[0] >> 16);
            float f2 = (float)(short)(vv[1] & 0xFFFFu);
            float f3 = (float)(short)(vv[1] >> 16);
            __nv_bfloat162 p0 = __floats2bfloat162_rn(f0, f1);
            __nv_bfloat162 p1 = __floats2bfloat162_rn(f2, f3);
            uint2 pk;
            pk.x = *(uint32_t*)&p0;
            pk.y = *(uint32_t*)&p1;
            *(uint2*)(base + (size_t)(i * 4 + j) * tstride) = pk;
        }
    }
}

// ---------------- PTX helpers ----------------
__device__ __forceinline__ void ldsm_x4(uint32_t addr, int& r0, int& r1, int& r2, int& r3) {
    asm volatile("ldmatrix.sync.aligned.m8n8.x4.shared.b16 {%0,%1,%2,%3}, [%4];\n"
                 : "=r"(r0), "=r"(r1), "=r"(r2), "=r"(r3) : "r"(addr));
}
#define MMA_BF16(d, A, B)                                                           \
    asm volatile("mma.sync.aligned.m16n8k16.row.col.f32.bf16.bf16.f32 "             \
                 "{%0,%1,%2,%3}, {%4,%5,%6,%7}, {%8,%9}, {%0,%1,%2,%3};\n"          \
                 : "+f"((d)[0]), "+f"((d)[1]), "+f"((d)[2]), "+f"((d)[3])           \
                 : "r"((A)[0]), "r"((A)[1]), "r"((A)[2]), "r"((A)[3]),              \
                   "r"((B)[0]), "r"((B)[1]))

__device__ __forceinline__ void bulk_cp(uint32_t dst, const void* src, uint32_t bytes, uint32_t mbar) {
    asm volatile(
        "cp.async.bulk.shared::cluster.global.mbarrier::complete_tx::bytes [%0], [%1], %2, [%3];\n"
        :: "r"(dst), "l"(src), "r"(bytes), "r"(mbar) : "memory");
}
__device__ __forceinline__ void mbar_init(uint32_t addr, uint32_t count) {
    asm volatile("mbarrier.init.shared.b64 [%0], %1;\n" :: "r"(addr), "r"(count) : "memory");
}
__device__ __forceinline__ void mbar_expect(uint32_t addr, uint32_t bytes) {
    asm volatile("mbarrier.arrive.expect_tx.shared.b64 _, [%0], %1;\n"
                 :: "r"(addr), "r"(bytes) : "memory");
}
__device__ __forceinline__ void mbar_wait(uint32_t addr, uint32_t parity) {
    uint32_t done = 0;
    while (!done) {
        asm volatile(
            "{\n\t.reg .pred p;\n\t"
            "mbarrier.try_wait.parity.acquire.cta.shared::cta.b64 p, [%1], %2, 0x989680;\n\t"
            "selp.b32 %0, 1, 0, p;\n\t}"
            : "=r"(done) : "r"(addr), "r"(parity) : "memory");
    }
}

// ---------------- winograd GEMM (bulk-copy pipeline) + fused output transform ----------------
__global__ __launch_bounds__(512, 1) void conv_kernel(float* __restrict__ out) {
    extern __shared__ __align__(1024) int8_t smem[];
    const uint32_t sbase  = (uint32_t)__cvta_generic_to_shared(smem);
    const uint32_t sMbar  = sbase;           // 2 mbarriers
    const uint32_t sStage = sbase + 1024;

    const int tid  = threadIdx.x;
    const int lane = tid & 31;
    const int wid  = tid >> 5;
    const int bn   = blockIdx.x;       // 0..1 (cout group)
    const int bm   = blockIdx.y;       // 0..391 (tile group)

    if (tid == 0) { mbar_init(sMbar, 1); mbar_init(sMbar + 8, 1); }
    __syncthreads();

    const uint8_t* Ag = (const uint8_t*)g_V + (size_t)bm * BM2 * 512;
    const uint8_t* Bg = (const uint8_t*)g_U + (size_t)bn * BNc * 512;

    auto issue = [&](int s) {
        if (tid == 0) {
            const uint32_t mb = sMbar + (s & 1) * 8;
            const uint32_t da = sStage + (s & 1) * STG;
            mbar_expect(mb, STG);
            bulk_cp(da,        Ag + (size_t)s * ((size_t)M2 * 512), A_ST, mb);
            bulk_cp(da + A_ST, Bg + (size_t)s * (CC * 512),         B_ST, mb);
        }
    };

    // ---- warp/fragment indexing: 16 warps as 4(m) x 4(n); warp tile 16x32
    const int wm  = (wid >> 2) * 16;
    const int wn  = (wid & 3) * 32;
    const int grp = lane >> 2;
    const int tig = lane & 3;

    const uint32_t rowA = wm + (lane & 15);
    const uint32_t hiA  = lane >> 4;
    const uint32_t rxA  = rowA & 7u;
    const uint32_t q    = lane >> 3;
    const uint32_t l8   = lane & 7;
    const uint32_t hiB  = q & 1;
    uint32_t rowB[2], rxB[2];
    #pragma unroll
    for (int p = 0; p < 2; p++) {
        rowB[p] = wn + p * 16 + (q >> 1) * 8 + l8;
        rxB[p]  = rowB[p] & 7u;
    }

    float acc[4][4];
    float oacc[2][2][4][4];
    #pragma unroll
    for (int ni = 0; ni < 4; ni++)
        #pragma unroll
        for (int r = 0; r < 4; r++) acc[ni][r] = 0.f;
    #pragma unroll
    for (int p = 0; p < 2; p++)
        #pragma unroll
        for (int qq = 0; qq < 2; qq++)
            #pragma unroll
            for (int ni = 0; ni < 4; ni++)
                #pragma unroll
                for (int r = 0; r < 4; r++) oacc[p][qq][ni][r] = 0.f;

    auto compute = [&](int buf) {
        const uint32_t abase = sStage + buf * STG + rowA * 512;
        uint32_t bbase[2];
        #pragma unroll
        for (int p = 0; p < 2; p++)
            bbase[p] = sStage + buf * STG + A_ST + rowB[p] * 512;
        #pragma unroll
        for (int j = 0; j < 16; j++) {
            const uint32_t uA = 2 * j + hiA;
            int a[4];
            ldsm_x4(abase + swz(uA, rxA) * 16, a[0], a[1], a[2], a[3]);
            int b[4][2];
            const uint32_t uB = 2 * j + hiB;
            #pragma unroll
            for (int p = 0; p < 2; p++)
                ldsm_x4(bbase[p] + swz(uB, rxB[p]) * 16,
                        b[2*p][0], b[2*p][1], b[2*p+1][0], b[2*p+1][1]);
            #pragma unroll
            for (int ni = 0; ni < 4; ni++)
                MMA_BF16(acc[ni], a, b[ni]);
        }
    };

    auto fold = [&](int t) {
        const int i = t >> 2, j = t & 3;
        const float ci0 = (i == 3) ? 0.f : 1.f;
        const float ci1 = (i == 0) ? 0.f : ((i == 1) ? 1.f : -1.f);
        const float cj0 = (j == 3) ? 0.f : 1.f;
        const float cj1 = (j == 0) ? 0.f : ((j == 1) ? 1.f : -1.f);
        const float cp[2] = {ci0, ci1};
        const float cq[2] = {cj0, cj1};
        #pragma unroll
        for (int p = 0; p < 2; p++)
            #pragma unroll
            for (int qq = 0; qq < 2; qq++) {
                const float c = cp[p] * cq[qq];
                if (c != 0.f) {
                    #pragma unroll
                    for (int ni = 0; ni < 4; ni++)
                        #pragma unroll
                        for (int r = 0; r < 4; r++)
                            oacc[p][qq][ni][r] += c * acc[ni][r];
                }
            }
        #pragma unroll
        for (int ni = 0; ni < 4; ni++)
            #pragma unroll
            for (int r = 0; r < 4; r++) acc[ni][r] = 0.f;
    };

    // ---- double-buffered bulk pipeline over 16 t-points
    issue(0);
    issue(1);
    for (int s = 0; s < 16; s++) {
        mbar_wait(sMbar + (s & 1) * 8, (s >> 1) & 1);
        compute(s & 1);
        fold(s);
        __syncthreads();
        if (s + 2 < 16) issue(s + 2);
    }

    // ---- epilogue: write 2x2 output pixels per tile row, scaled by 1/9
    const float inv9 = 1.0f / 9.0f;
    #pragma unroll
    for (int half = 0; half < 2; half++) {
        const int mrow  = bm * BM2 + wm + grp + half * 8;
        const int n_img = mrow / TILES;
        const int rr    = mrow - n_img * TILES;
        const int th    = rr / 28;
        const int tw    = rr - th * 28;
        #pragma unroll
        for (int p = 0; p < 2; p++) {
            const int oh = 2 * th + p;
            #pragma unroll
            for (int qq = 0; qq < 2; qq++) {
                const int ow = 2 * tw + qq;
                float* orow = out + (size_t)(n_img * HW + oh * WW + ow) * CC
                            + bn * BNc + wn + tig * 2;
                #pragma unroll
                for (int ni = 0; ni < 4; ni++) {
                    float2 v;
                    v.x = oacc[p][qq][ni][half * 2 + 0] * inv9;
                    v.y = oacc[p][qq][ni][half * 2 + 1] * inv9;
                    *(float2*)&orow[ni * 8] = v;
                }
            }
        }
    }
}

// ---------------- launch ----------------
extern "C" void kernel_launch(void* const* d_in, const int* in_sizes, int n_in,
                              void* d_out, int out_size) {
    const float* x = (const float*)d_in[0];
    const float* w = (const float*)d_in[1];
    if (n_in >= 2 && in_sizes[0] == CC * 9 * CC) {
        x = (const float*)d_in[1];
        w = (const float*)d_in[0];
    }
    float* out = (float*)d_out;

    cudaFuncSetAttribute(conv_kernel, cudaFuncAttributeMaxDynamicSharedMemorySize, SMEM_TOTAL);

    wmax_kernel<<<1024, 256>>>(w);
    utrans_kernel<<<256, 256>>>(w);
    vtrans_kernel<<<M2 / 4, 256>>>(x);
    conv_kernel<<<dim3(2, M2 / BM2), 512, SMEM_TOTAL>>>(out);
}

// round 14
// speedup vs baseline: 1.3781x; 1.1605x over previous
#include <cuda_runtime.h>
#include <cuda_bf16.h>
#include <cstdint>

#define NB 32
#define HH 56
#define WW 56
#define CC 256
#define HW (HH*WW)           // 3136
#define M_TOTAL (NB*HW)      // 100352
#define TILES 784            // 28*28 tiles per image
#define M2 (NB*TILES)        // 25088 winograd tiles

#define BM2 64               // tiles per CTA
#define BNc 128              // couts per CTA
#define A_ST (BM2*512)       // 32768
#define B_ST (BNc*512)       // 65536
#define STG (A_ST+B_ST)      // 98304
#define SMEM_TOTAL (1024 + 2*STG)   // 197632

__device__ __align__(16) __nv_bfloat16 g_V[(size_t)16 * M2 * CC];    // [t][m2][cin] swizzled rows
__device__ __align__(16) __nv_bfloat16 g_U[(size_t)16 * CC * CC];    // [t][cout][cin] swizzled rows
__device__ unsigned int g_wmax_bits;   // idempotent across replays (same input)

// row-internal swizzle: 16B-unit u (0..31), row low bits rx
__device__ __forceinline__ uint32_t swz(uint32_t u, uint32_t rx) {
    return (u & 24u) | ((u ^ rx) & 7u);
}

// ---------------- prologue kernels ----------------
// max|w| only — tanh is monotonic, so tanh(max|w|) = max|tanh(w)| (applied in utrans)
__global__ void wmax_kernel(const float* __restrict__ w) {
    int i0 = blockIdx.x * blockDim.x + threadIdx.x;
    int stride = gridDim.x * blockDim.x;
    float m = 0.f;
    for (int i = i0; i < CC * 9 * CC; i += stride)
        m = fmaxf(m, fabsf(w[i]));
    #pragma unroll
    for (int off = 16; off > 0; off >>= 1)
        m = fmaxf(m, __shfl_xor_sync(0xffffffffu, m, off));
    if ((threadIdx.x & 31) == 0)
        atomicMax(&g_wmax_bits, __float_as_uint(m));
}

// weight transform: quantize + U = G g G^T (multiples of 1/4, exact in bf16)
__global__ void utrans_kernel(const float* __restrict__ w) {
    const int idx  = blockIdx.x * 256 + threadIdx.x;   // 65536
    const int cout = idx & 255;
    const int cin  = idx >> 8;
    const float mx = tanhf(__uint_as_float(g_wmax_bits));
    float g[3][3];
    #pragma unroll
    for (int ky = 0; ky < 3; ky++)
        #pragma unroll
        for (int kx = 0; kx < 3; kx++) {
            float t  = tanhf(w[((ky * 3 + kx) * CC + cin) * CC + cout]);
            float tn = t / mx * 0.5f + 0.5f;
            float kq = rintf(tn * 3.0f);
            kq = fminf(fmaxf(kq, 0.f), 3.f);
            g[ky][kx] = 2.0f * kq - 3.0f;
        }
    float R[3][4];
    #pragma unroll
    for (int ky = 0; ky < 3; ky++) {
        R[ky][0] = g[ky][0];
        R[ky][1] = 0.5f * (g[ky][0] + g[ky][1] + g[ky][2]);
        R[ky][2] = 0.5f * (g[ky][0] - g[ky][1] + g[ky][2]);
        R[ky][3] = g[ky][2];
    }
    const uint32_t off = swz((uint32_t)cin >> 3, (uint32_t)cout & 7u) * 16
                       + ((uint32_t)cin & 7u) * 2;
    uint8_t* base = (uint8_t*)g_U + (size_t)cout * 512 + off;
    #pragma unroll
    for (int j = 0; j < 4; j++) {
        float u0 = R[0][j];
        float u1 = 0.5f * (R[0][j] + R[1][j] + R[2][j]);
        float u2 = 0.5f * (R[0][j] - R[1][j] + R[2][j]);
        float u3 = R[2][j];
        *(__nv_bfloat16*)(base + (size_t)(0 * 4 + j) * (CC * 512)) = __float2bfloat16(u0);
        *(__nv_bfloat16*)(base + (size_t)(1 * 4 + j) * (CC * 512)) = __float2bfloat16(u1);
        *(__nv_bfloat16*)(base + (size_t)(2 * 4 + j) * (CC * 512)) = __float2bfloat16(u2);
        *(__nv_bfloat16*)(base + (size_t)(3 * 4 + j) * (CC * 512)) = __float2bfloat16(u3);
    }
}

// fused activation quantize + input transform: V = B^T quant(d) B
__global__ void vtrans_kernel(const float* __restrict__ x) {
    const int m2 = blockIdx.x * 4 + (threadIdx.x >> 6);   // 4 tiles per 256-thr block
    const int c4 = threadIdx.x & 63;                      // cins 4*c4 .. 4*c4+3
    const int n   = m2 / TILES;
    const int r   = m2 - n * TILES;
    const int th  = r / 28;
    const int tw  = r - th * 28;
    const int ih0 = 2 * th - 1, iw0 = 2 * tw - 1;
    const float* xb = x + ((size_t)n * HW) * CC + c4 * 4;

    uint32_t d[4][4][2];
    #pragma unroll
    for (int a = 0; a < 4; a++) {
        const int ih = ih0 + a;
        #pragma unroll
        for (int b = 0; b < 4; b++) {
            const int iw = iw0 + b;
            const bool ok = ((unsigned)ih < HH) && ((unsigned)iw < WW);
            if (ok) {
                float4 v = *(const float4*)(xb + (size_t)(ih * WW + iw) * CC);
                uint32_t q0 = (uint32_t)(int)rintf(fminf(fmaxf(v.x, 0.f), 1.f) * 3.0f);
                uint32_t q1 = (uint32_t)(int)rintf(fminf(fmaxf(v.y, 0.f), 1.f) * 3.0f);
                uint32_t q2 = (uint32_t)(int)rintf(fminf(fmaxf(v.z, 0.f), 1.f) * 3.0f);
                uint32_t q3 = (uint32_t)(int)rintf(fminf(fmaxf(v.w, 0.f), 1.f) * 3.0f);
                d[a][b][0] = q0 | (q1 << 16);
                d[a][b][1] = q2 | (q3 << 16);
            } else {
                d[a][b][0] = 0u;
                d[a][b][1] = 0u;
            }
        }
    }

    const uint32_t off = swz((uint32_t)c4 >> 1, (uint32_t)m2 & 7u) * 16
                       + ((uint32_t)c4 & 1u) * 8;
    uint8_t* base = (uint8_t*)g_V + (size_t)m2 * 512 + off;
    const size_t tstride = (size_t)M2 * 512;

    #pragma unroll
    for (int j = 0; j < 4; j++) {
        uint32_t tj[4][2];
        #pragma unroll
        for (int a = 0; a < 4; a++) {
            #pragma unroll
            for (int h = 0; h < 2; h++) {
                uint32_t t;
                if (j == 0)      t = __vsub2(d[a][0][h], d[a][2][h]);
                else if (j == 1) t = __vadd2(d[a][1][h], d[a][2][h]);
                else if (j == 2) t = __vsub2(d[a][2][h], d[a][1][h]);
                else             t = __vsub2(d[a][1][h], d[a][3][h]);
                tj[a][h] = t;
            }
        }
        #pragma unroll
        for (int i = 0; i < 4; i++) {
            uint32_t vv[2];
            #pragma unroll
            for (int h = 0; h < 2; h++) {
                if (i == 0)      vv[h] = __vsub2(tj[0][h], tj[2][h]);
                else if (i == 1) vv[h] = __vadd2(tj[1][h], tj[2][h]);
                else if (i == 2) vv[h] = __vsub2(tj[2][h], tj[1][h]);
                else             vv[h] = __vsub2(tj[1][h], tj[3][h]);
            }
            float f0 = (float)(short)(vv[0] & 0xFFFFu);
            float f1 = (float)(short)(vv[0] >> 16);
            float f2 = (float)(short)(vv[1] & 0xFFFFu);
            float f3 = (float)(short)(vv[1] >> 16);
            __nv_bfloat162 p0 = __floats2bfloat162_rn(f0, f1);
            __nv_bfloat162 p1 = __floats2bfloat162_rn(f2, f3);
            uint2 pk;
            pk.x = *(uint32_t*)&p0;
            pk.y = *(uint32_t*)&p1;
            *(uint2*)(base + (size_t)(i * 4 + j) * tstride) = pk;
        }
    }
}

// ---------------- PTX helpers ----------------
__device__ __forceinline__ void ldsm_x4(uint32_t addr, int& r0, int& r1, int& r2, int& r3) {
    asm volatile("ldmatrix.sync.aligned.m8n8.x4.shared.b16 {%0,%1,%2,%3}, [%4];\n"
                 : "=r"(r0), "=r"(r1), "=r"(r2), "=r"(r3) : "r"(addr));
}
#define MMA_BF16(d, A, B)                                                           \
    asm volatile("mma.sync.aligned.m16n8k16.row.col.f32.bf16.bf16.f32 "             \
                 "{%0,%1,%2,%3}, {%4,%5,%6,%7}, {%8,%9}, {%0,%1,%2,%3};\n"          \
                 : "+f"((d)[0]), "+f"((d)[1]), "+f"((d)[2]), "+f"((d)[3])           \
                 : "r"((A)[0]), "r"((A)[1]), "r"((A)[2]), "r"((A)[3]),              \
                   "r"((B)[0]), "r"((B)[1]))

__device__ __forceinline__ void bulk_cp(uint32_t dst, const void* src, uint32_t bytes, uint32_t mbar) {
    asm volatile(
        "cp.async.bulk.shared::cluster.global.mbarrier::complete_tx::bytes [%0], [%1], %2, [%3];\n"
        :: "r"(dst), "l"(src), "r"(bytes), "r"(mbar) : "memory");
}
__device__ __forceinline__ void mbar_init(uint32_t addr, uint32_t count) {
    asm volatile("mbarrier.init.shared.b64 [%0], %1;\n" :: "r"(addr), "r"(count) : "memory");
}
__device__ __forceinline__ void mbar_expect(uint32_t addr, uint32_t bytes) {
    asm volatile("mbarrier.arrive.expect_tx.shared.b64 _, [%0], %1;\n"
                 :: "r"(addr), "r"(bytes) : "memory");
}
__device__ __forceinline__ void mbar_wait(uint32_t addr, uint32_t parity) {
    uint32_t done = 0;
    while (!done) {
        asm volatile(
            "{\n\t.reg .pred p;\n\t"
            "mbarrier.try_wait.parity.acquire.cta.shared::cta.b64 p, [%1], %2, 0x989680;\n\t"
            "selp.b32 %0, 1, 0, p;\n\t}"
            : "=r"(done) : "r"(addr), "r"(parity) : "memory");
    }
}

// ---------------- winograd GEMM (bulk pipeline, 8 warps, 32x32 warp tiles) ----------------
__global__ __launch_bounds__(256, 1) void conv_kernel(float* __restrict__ out) {
    extern __shared__ __align__(1024) int8_t smem[];
    const uint32_t sbase  = (uint32_t)__cvta_generic_to_shared(smem);
    const uint32_t sMbar  = sbase;           // 2 mbarriers
    const uint32_t sStage = sbase + 1024;

    const int tid  = threadIdx.x;
    const int lane = tid & 31;
    const int wid  = tid >> 5;
    const int bn   = blockIdx.x;       // 0..1 (cout group)
    const int bm   = blockIdx.y;       // 0..391 (tile group)

    if (tid == 0) { mbar_init(sMbar, 1); mbar_init(sMbar + 8, 1); }
    __syncthreads();

    const uint8_t* Ag = (const uint8_t*)g_V + (size_t)bm * BM2 * 512;
    const uint8_t* Bg = (const uint8_t*)g_U + (size_t)bn * BNc * 512;

    auto issue = [&](int s) {
        if (tid == 0) {
            const uint32_t mb = sMbar + (s & 1) * 8;
            const uint32_t da = sStage + (s & 1) * STG;
            mbar_expect(mb, STG);
            bulk_cp(da,        Ag + (size_t)s * ((size_t)M2 * 512), A_ST, mb);
            bulk_cp(da + A_ST, Bg + (size_t)s * (CC * 512),         B_ST, mb);
        }
    };

    // ---- warp/fragment indexing: 8 warps as 2(m) x 4(n); warp tile 32x32
    const int wm  = (wid >> 2) * 32;
    const int wn  = (wid & 3) * 32;
    const int grp = lane >> 2;
    const int tig = lane & 3;

    const uint32_t rowA0 = wm + (lane & 15);      // mi=0 rows; mi=1 at +16
    const uint32_t hiA   = lane >> 4;
    const uint32_t rxA   = rowA0 & 7u;            // same low bits for rowA0+16
    const uint32_t q     = lane >> 3;
    const uint32_t l8    = lane & 7;
    const uint32_t hiB   = q & 1;
    uint32_t rowB[2], rxB[2];
    #pragma unroll
    for (int p = 0; p < 2; p++) {
        rowB[p] = wn + p * 16 + (q >> 1) * 8 + l8;
        rxB[p]  = rowB[p] & 7u;
    }

    float acc[2][4][4];                   // [mi][ni][r]
    float oacc[2][2][2][4][4];            // [p][q][mi][ni][r]
    #pragma unroll
    for (int mi = 0; mi < 2; mi++)
        #pragma unroll
        for (int ni = 0; ni < 4; ni++)
            #pragma unroll
            for (int r = 0; r < 4; r++) acc[mi][ni][r] = 0.f;
    #pragma unroll
    for (int p = 0; p < 2; p++)
        #pragma unroll
        for (int qq = 0; qq < 2; qq++)
            #pragma unroll
            for (int mi = 0; mi < 2; mi++)
                #pragma unroll
                for (int ni = 0; ni < 4; ni++)
                    #pragma unroll
                    for (int r = 0; r < 4; r++) oacc[p][qq][mi][ni][r] = 0.f;

    auto compute = [&](int buf) {
        const uint32_t so = sStage + buf * STG;
        uint32_t abase[2];
        abase[0] = so + rowA0 * 512;
        abase[1] = so + (rowA0 + 16) * 512;
        uint32_t bbase[2];
        #pragma unroll
        for (int p = 0; p < 2; p++)
            bbase[p] = so + A_ST + rowB[p] * 512;
        #pragma unroll
        for (int j = 0; j < 16; j++) {
            const uint32_t uA = 2 * j + hiA;
            int a[2][4];
            #pragma unroll
            for (int mi = 0; mi < 2; mi++)
                ldsm_x4(abase[mi] + swz(uA, rxA) * 16,
                        a[mi][0], a[mi][1], a[mi][2], a[mi][3]);
            const uint32_t uB = 2 * j + hiB;
            int b[4][2];
            #pragma unroll
            for (int p = 0; p < 2; p++)
                ldsm_x4(bbase[p] + swz(uB, rxB[p]) * 16,
                        b[2*p][0], b[2*p][1], b[2*p+1][0], b[2*p+1][1]);
            #pragma unroll
            for (int mi = 0; mi < 2; mi++)
                #pragma unroll
                for (int ni = 0; ni < 4; ni++)
                    MMA_BF16(acc[mi][ni], a[mi], b[ni]);
        }
    };

    auto fold = [&](int t) {
        const int i = t >> 2, j = t & 3;
        const float ci0 = (i == 3) ? 0.f : 1.f;
        const float ci1 = (i == 0) ? 0.f : ((i == 1) ? 1.f : -1.f);
        const float cj0 = (j == 3) ? 0.f : 1.f;
        const float cj1 = (j == 0) ? 0.f : ((j == 1) ? 1.f : -1.f);
        const float cp[2] = {ci0, ci1};
        const float cq[2] = {cj0, cj1};
        #pragma unroll
        for (int p = 0; p < 2; p++)
            #pragma unroll
            for (int qq = 0; qq < 2; qq++) {
                const float c = cp[p] * cq[qq];
                if (c != 0.f) {
                    #pragma unroll
                    for (int mi = 0; mi < 2; mi++)
                        #pragma unroll
                        for (int ni = 0; ni < 4; ni++)
                            #pragma unroll
                            for (int r = 0; r < 4; r++)
                                oacc[p][qq][mi][ni][r] += c * acc[mi][ni][r];
                }
            }
        #pragma unroll
        for (int mi = 0; mi < 2; mi++)
            #pragma unroll
            for (int ni = 0; ni < 4; ni++)
                #pragma unroll
                for (int r = 0; r < 4; r++) acc[mi][ni][r] = 0.f;
    };

    // ---- double-buffered bulk pipeline over 16 t-points
    issue(0);
    issue(1);
    for (int s = 0; s < 16; s++) {
        mbar_wait(sMbar + (s & 1) * 8, (s >> 1) & 1);
        compute(s & 1);
        fold(s);
        __syncthreads();
        if (s + 2 < 16) issue(s + 2);
    }

    // ---- epilogue: write 2x2 output pixels per tile row, scaled by 1/9
    const float inv9 = 1.0f / 9.0f;
    #pragma unroll
    for (int mi = 0; mi < 2; mi++) {
        #pragma unroll
        for (int half = 0; half < 2; half++) {
            const int mrow  = bm * BM2 + wm + mi * 16 + grp + half * 8;
            const int n_img = mrow / TILES;
            const int rr    = mrow - n_img * TILES;
            const int th    = rr / 28;
            const int tw    = rr - th * 28;
            #pragma unroll
            for (int p = 0; p < 2; p++) {
                const int oh = 2 * th + p;
                #pragma unroll
                for (int qq = 0; qq < 2; qq++) {
                    const int ow = 2 * tw + qq;
                    float* orow = out + (size_t)(n_img * HW + oh * WW + ow) * CC
                                + bn * BNc + wn + tig * 2;
                    #pragma unroll
                    for (int ni = 0; ni < 4; ni++) {
                        float2 v;
                        v.x = oacc[p][qq][mi][ni][half * 2 + 0] * inv9;
                        v.y = oacc[p][qq][mi][ni][half * 2 + 1] * inv9;
                        *(float2*)&orow[ni * 8] = v;
                    }
                }
            }
        }
    }
}

// ---------------- launch ----------------
extern "C" void kernel_launch(void* const* d_in, const int* in_sizes, int n_in,
                              void* d_out, int out_size) {
    const float* x = (const float*)d_in[0];
    const float* w = (const float*)d_in[1];
    if (n_in >= 2 && in_sizes[0] == CC * 9 * CC) {
        x = (const float*)d_in[1];
        w = (const float*)d_in[0];
    }
    float* out = (float*)d_out;

    cudaFuncSetAttribute(conv_kernel, cudaFuncAttributeMaxDynamicSharedMemorySize, SMEM_TOTAL);

    wmax_kernel<<<1024, 256>>>(w);
    utrans_kernel<<<256, 256>>>(w);
    vtrans_kernel<<<M2 / 4, 256>>>(x);
    conv_kernel<<<dim3(2, M2 / BM2), 256, SMEM_TOTAL>>>(out);
}

// round 15
// speedup vs baseline: 1.4420x; 1.0464x over previous
#include <cuda_runtime.h>
#include <cuda_bf16.h>
#include <cstdint>

#define NB 32
#define HH 56
#define WW 56
#define CC 256
#define HW (HH*WW)           // 3136
#define M_TOTAL (NB*HW)      // 100352
#define TILES 784            // 28*28 tiles per image
#define M2 (NB*TILES)        // 25088 winograd tiles

#define BM2 64               // tiles per CTA
#define BNc 128              // couts per CTA
#define A_ST (BM2*512)       // 32768
#define B_ST (BNc*512)       // 65536
#define STG (A_ST+B_ST)      // 98304
#define SMEM_TOTAL (1024 + 2*STG)   // 197632

__device__ __align__(16) __nv_bfloat16 g_V[(size_t)16 * M2 * CC];    // [t][m2][cin] swizzled rows
__device__ __align__(16) __nv_bfloat16 g_U[(size_t)16 * CC * CC];    // [t][cout][cin] swizzled rows
__device__ unsigned int g_wmax_bits;   // idempotent across replays (same input)

// row-internal swizzle: 16B-unit u (0..31), row low bits rx
__device__ __forceinline__ uint32_t swz(uint32_t u, uint32_t rx) {
    return (u & 24u) | ((u ^ rx) & 7u);
}

// ---------------- prologue kernels ----------------
__global__ void wmax_kernel(const float* __restrict__ w) {
    int i0 = blockIdx.x * blockDim.x + threadIdx.x;
    int stride = gridDim.x * blockDim.x;
    float m = 0.f;
    for (int i = i0; i < CC * 9 * CC; i += stride)
        m = fmaxf(m, fabsf(w[i]));
    #pragma unroll
    for (int off = 16; off > 0; off >>= 1)
        m = fmaxf(m, __shfl_xor_sync(0xffffffffu, m, off));
    if ((threadIdx.x & 31) == 0)
        atomicMax(&g_wmax_bits, __float_as_uint(m));
}

__global__ void utrans_kernel(const float* __restrict__ w) {
    const int idx  = blockIdx.x * 256 + threadIdx.x;   // 65536
    const int cout = idx & 255;
    const int cin  = idx >> 8;
    const float mx = tanhf(__uint_as_float(g_wmax_bits));
    float g[3][3];
    #pragma unroll
    for (int ky = 0; ky < 3; ky++)
        #pragma unroll
        for (int kx = 0; kx < 3; kx++) {
            float t  = tanhf(w[((ky * 3 + kx) * CC + cin) * CC + cout]);
            float tn = t / mx * 0.5f + 0.5f;
            float kq = rintf(tn * 3.0f);
            kq = fminf(fmaxf(kq, 0.f), 3.f);
            g[ky][kx] = 2.0f * kq - 3.0f;
        }
    float R[3][4];
    #pragma unroll
    for (int ky = 0; ky < 3; ky++) {
        R[ky][0] = g[ky][0];
        R[ky][1] = 0.5f * (g[ky][0] + g[ky][1] + g[ky][2]);
        R[ky][2] = 0.5f * (g[ky][0] - g[ky][1] + g[ky][2]);
        R[ky][3] = g[ky][2];
    }
    const uint32_t off = swz((uint32_t)cin >> 3, (uint32_t)cout & 7u) * 16
                       + ((uint32_t)cin & 7u) * 2;
    uint8_t* base = (uint8_t*)g_U + (size_t)cout * 512 + off;
    #pragma unroll
    for (int j = 0; j < 4; j++) {
        float u0 = R[0][j];
        float u1 = 0.5f * (R[0][j] + R[1][j] + R[2][j]);
        float u2 = 0.5f * (R[0][j] - R[1][j] + R[2][j]);
        float u3 = R[2][j];
        *(__nv_bfloat16*)(base + (size_t)(0 * 4 + j) * (CC * 512)) = __float2bfloat16(u0);
        *(__nv_bfloat16*)(base + (size_t)(1 * 4 + j) * (CC * 512)) = __float2bfloat16(u1);
        *(__nv_bfloat16*)(base + (size_t)(2 * 4 + j) * (CC * 512)) = __float2bfloat16(u2);
        *(__nv_bfloat16*)(base + (size_t)(3 * 4 + j) * (CC * 512)) = __float2bfloat16(u3);
    }
}

// fused activation quantize + input transform: V = B^T quant(d) B
__global__ void vtrans_kernel(const float* __restrict__ x) {
    const int m2 = blockIdx.x * 4 + (threadIdx.x >> 6);
    const int c4 = threadIdx.x & 63;
    const int n   = m2 / TILES;
    const int r   = m2 - n * TILES;
    const int th  = r / 28;
    const int tw  = r - th * 28;
    const int ih0 = 2 * th - 1, iw0 = 2 * tw - 1;
    const float* xb = x + ((size_t)n * HW) * CC + c4 * 4;

    uint32_t d[4][4][2];
    #pragma unroll
    for (int a = 0; a < 4; a++) {
        const int ih = ih0 + a;
        #pragma unroll
        for (int b = 0; b < 4; b++) {
            const int iw = iw0 + b;
            const bool ok = ((unsigned)ih < HH) && ((unsigned)iw < WW);
            if (ok) {
                float4 v = *(const float4*)(xb + (size_t)(ih * WW + iw) * CC);
                uint32_t q0 = (uint32_t)(int)rintf(fminf(fmaxf(v.x, 0.f), 1.f) * 3.0f);
                uint32_t q1 = (uint32_t)(int)rintf(fminf(fmaxf(v.y, 0.f), 1.f) * 3.0f);
                uint32_t q2 = (uint32_t)(int)rintf(fminf(fmaxf(v.z, 0.f), 1.f) * 3.0f);
                uint32_t q3 = (uint32_t)(int)rintf(fminf(fmaxf(v.w, 0.f), 1.f) * 3.0f);
                d[a][b][0] = q0 | (q1 << 16);
                d[a][b][1] = q2 | (q3 << 16);
            } else {
                d[a][b][0] = 0u;
                d[a][b][1] = 0u;
            }
        }
    }

    const uint32_t off = swz((uint32_t)c4 >> 1, (uint32_t)m2 & 7u) * 16
                       + ((uint32_t)c4 & 1u) * 8;
    uint8_t* base = (uint8_t*)g_V + (size_t)m2 * 512 + off;
    const size_t tstride = (size_t)M2 * 512;

    #pragma unroll
    for (int j = 0; j < 4; j++) {
        uint32_t tj[4][2];
        #pragma unroll
        for (int a = 0; a < 4; a++) {
            #pragma unroll
            for (int h = 0; h < 2; h++) {
                uint32_t t;
                if (j == 0)      t = __vsub2(d[a][0][h], d[a][2][h]);
                else if (j == 1) t = __vadd2(d[a][1][h], d[a][2][h]);
                else if (j == 2) t = __vsub2(d[a][2][h], d[a][1][h]);
                else             t = __vsub2(d[a][1][h], d[a][3][h]);
                tj[a][h] = t;
            }
        }
        #pragma unroll
        for (int i = 0; i < 4; i++) {
            uint32_t vv[2];
            #pragma unroll
            for (int h = 0; h < 2; h++) {
                if (i == 0)      vv[h] = __vsub2(tj[0][h], tj[2][h]);
                else if (i == 1) vv[h] = __vadd2(tj[1][h], tj[2][h]);
                else if (i == 2) vv[h] = __vsub2(tj[2][h], tj[1][h]);
                else             vv[h] = __vsub2(tj[1][h], tj[3][h]);
            }
            float f0 = (float)(short)(vv[0] & 0xFFFFu);
            float f1 = (float)(short)(vv[0] >> 16);
            float f2 = (float)(short)(vv[1] & 0xFFFFu);
            float f3 = (float)(short)(vv[1] >> 16);
            __nv_bfloat162 p0 = __floats2bfloat162_rn(f0, f1);
            __nv_bfloat162 p1 = __floats2bfloat162_rn(f2, f3);
            uint2 pk;
            pk.x = *(uint32_t*)&p0;
            pk.y = *(uint32_t*)&p1;
            *(uint2*)(base + (size_t)(i * 4 + j) * tstride) = pk;
        }
    }
}

// ---------------- PTX helpers ----------------
__device__ __forceinline__ void ldsm_x4(uint32_t addr, int& r0, int& r1, int& r2, int& r3) {
    asm volatile("ldmatrix.sync.aligned.m8n8.x4.shared.b16 {%0,%1,%2,%3}, [%4];\n"
                 : "=r"(r0), "=r"(r1), "=r"(r2), "=r"(r3) : "r"(addr));
}
#define MMA_BF16(d, A, B)                                                           \
    asm volatile("mma.sync.aligned.m16n8k16.row.col.f32.bf16.bf16.f32 "             \
                 "{%0,%1,%2,%3}, {%4,%5,%6,%7}, {%8,%9}, {%0,%1,%2,%3};\n"          \
                 : "+f"((d)[0]), "+f"((d)[1]), "+f"((d)[2]), "+f"((d)[3])           \
                 : "r"((A)[0]), "r"((A)[1]), "r"((A)[2]), "r"((A)[3]),              \
                   "r"((B)[0]), "r"((B)[1]))

__device__ __forceinline__ void bulk_cp(uint32_t dst, const void* src, uint32_t bytes, uint32_t mbar) {
    asm volatile(
        "cp.async.bulk.shared::cluster.global.mbarrier::complete_tx::bytes [%0], [%1], %2, [%3];\n"
        :: "r"(dst), "l"(src), "r"(bytes), "r"(mbar) : "memory");
}
__device__ __forceinline__ void mbar_init(uint32_t addr, uint32_t count) {
    asm volatile("mbarrier.init.shared.b64 [%0], %1;\n" :: "r"(addr), "r"(count) : "memory");
}
__device__ __forceinline__ void mbar_expect(uint32_t addr, uint32_t bytes) {
    asm volatile("mbarrier.arrive.expect_tx.shared.b64 _, [%0], %1;\n"
                 :: "r"(addr), "r"(bytes) : "memory");
}
__device__ __forceinline__ void mbar_arrive(uint32_t addr) {
    asm volatile("mbarrier.arrive.shared.b64 _, [%0];\n" :: "r"(addr) : "memory");
}
__device__ __forceinline__ void mbar_wait(uint32_t addr, uint32_t parity) {
    uint32_t done = 0;
    while (!done) {
        asm volatile(
            "{\n\t.reg .pred p;\n\t"
            "mbarrier.try_wait.parity.acquire.cta.shared::cta.b64 p, [%1], %2, 0x989680;\n\t"
            "selp.b32 %0, 1, 0, p;\n\t}"
            : "=r"(done) : "r"(addr), "r"(parity) : "memory");
    }
}

// ---------------- winograd GEMM (drift pipeline, 8 warps, 32x32 warp tiles) ----------------
__global__ __launch_bounds__(256, 1) void conv_kernel(float* __restrict__ out) {
    extern __shared__ __align__(1024) int8_t smem[];
    const uint32_t sbase  = (uint32_t)__cvta_generic_to_shared(smem);
    const uint32_t sFull  = sbase;           // 2 full mbarriers (tx-based)
    const uint32_t sEmpty = sbase + 16;      // 2 empty mbarriers (count 256)
    const uint32_t sStage = sbase + 1024;

    const int tid  = threadIdx.x;
    const int lane = tid & 31;
    const int wid  = tid >> 5;
    const int bn   = blockIdx.x;       // 0..1 (cout group)
    const int bm   = blockIdx.y;       // 0..391 (tile group)

    if (tid == 0) {
        mbar_init(sFull, 1);      mbar_init(sFull + 8, 1);
        mbar_init(sEmpty, 256);   mbar_init(sEmpty + 8, 256);
    }
    __syncthreads();

    const uint8_t* Ag = (const uint8_t*)g_V + (size_t)bm * BM2 * 512;
    const uint8_t* Bg = (const uint8_t*)g_U + (size_t)bn * BNc * 512;

    auto issue = [&](int s) {
        const uint32_t mb = sFull + (s & 1) * 8;
        const uint32_t da = sStage + (s & 1) * STG;
        mbar_expect(mb, STG);
        bulk_cp(da,        Ag + (size_t)s * ((size_t)M2 * 512), A_ST, mb);
        bulk_cp(da + A_ST, Bg + (size_t)s * (CC * 512),         B_ST, mb);
    };

    // ---- warp/fragment indexing: 8 warps as 2(m) x 4(n); warp tile 32x32
    const int wm  = (wid >> 2) * 32;
    const int wn  = (wid & 3) * 32;
    const int grp = lane >> 2;
    const int tig = lane & 3;

    const uint32_t rowA0 = wm + (lane & 15);
    const uint32_t hiA   = lane >> 4;
    const uint32_t rxA   = rowA0 & 7u;
    const uint32_t q     = lane >> 3;
    const uint32_t l8    = lane & 7;
    const uint32_t hiB   = q & 1;
    uint32_t rowB[2], rxB[2];
    #pragma unroll
    for (int p = 0; p < 2; p++) {
        rowB[p] = wn + p * 16 + (q >> 1) * 8 + l8;
        rxB[p]  = rowB[p] & 7u;
    }

    float acc[2][4][4];
    float oacc[2][2][2][4][4];
    #pragma unroll
    for (int mi = 0; mi < 2; mi++)
        #pragma unroll
        for (int ni = 0; ni < 4; ni++)
            #pragma unroll
            for (int r = 0; r < 4; r++) acc[mi][ni][r] = 0.f;
    #pragma unroll
    for (int p = 0; p < 2; p++)
        #pragma unroll
        for (int qq = 0; qq < 2; qq++)
            #pragma unroll
            for (int mi = 0; mi < 2; mi++)
                #pragma unroll
                for (int ni = 0; ni < 4; ni++)
                    #pragma unroll
                    for (int r = 0; r < 4; r++) oacc[p][qq][mi][ni][r] = 0.f;

    auto compute = [&](int buf) {
        const uint32_t so = sStage + buf * STG;
        uint32_t abase[2];
        abase[0] = so + rowA0 * 512;
        abase[1] = so + (rowA0 + 16) * 512;
        uint32_t bbase[2];
        #pragma unroll
        for (int p = 0; p < 2; p++)
            bbase[p] = so + A_ST + rowB[p] * 512;

        // software-pipelined B fragments: load b(j+1) during MMAs of j
        int bf[4][2];
        ldsm_x4(bbase[0] + swz(hiB, rxB[0]) * 16, bf[0][0], bf[0][1], bf[1][0], bf[1][1]);
        ldsm_x4(bbase[1] + swz(hiB, rxB[1]) * 16, bf[2][0], bf[2][1], bf[3][0], bf[3][1]);
        #pragma unroll
        for (int j = 0; j < 16; j++) {
            const uint32_t uA = 2 * j + hiA;
            int a[2][4];
            #pragma unroll
            for (int mi = 0; mi < 2; mi++)
                ldsm_x4(abase[mi] + swz(uA, rxA) * 16,
                        a[mi][0], a[mi][1], a[mi][2], a[mi][3]);
            int bnx[4][2];
            if (j < 15) {
                const uint32_t uB = 2 * (j + 1) + hiB;
                ldsm_x4(bbase[0] + swz(uB, rxB[0]) * 16,
                        bnx[0][0], bnx[0][1], bnx[1][0], bnx[1][1]);
                ldsm_x4(bbase[1] + swz(uB, rxB[1]) * 16,
                        bnx[2][0], bnx[2][1], bnx[3][0], bnx[3][1]);
            }
            #pragma unroll
            for (int mi = 0; mi < 2; mi++)
                #pragma unroll
                for (int ni = 0; ni < 4; ni++)
                    MMA_BF16(acc[mi][ni], a[mi], bf[ni]);
            if (j < 15) {
                #pragma unroll
                for (int ni = 0; ni < 4; ni++) {
                    bf[ni][0] = bnx[ni][0];
                    bf[ni][1] = bnx[ni][1];
                }
            }
        }
    };

    auto fold = [&](int t) {
        const int i = t >> 2, j = t & 3;
        const float ci0 = (i == 3) ? 0.f : 1.f;
        const float ci1 = (i == 0) ? 0.f : ((i == 1) ? 1.f : -1.f);
        const float cj0 = (j == 3) ? 0.f : 1.f;
        const float cj1 = (j == 0) ? 0.f : ((j == 1) ? 1.f : -1.f);
        const float cp[2] = {ci0, ci1};
        const float cq[2] = {cj0, cj1};
        #pragma unroll
        for (int p = 0; p < 2; p++)
            #pragma unroll
            for (int qq = 0; qq < 2; qq++) {
                const float c = cp[p] * cq[qq];
                if (c != 0.f) {
                    #pragma unroll
                    for (int mi = 0; mi < 2; mi++)
                        #pragma unroll
                        for (int ni = 0; ni < 4; ni++)
                            #pragma unroll
                            for (int r = 0; r < 4; r++)
                                oacc[p][qq][mi][ni][r] += c * acc[mi][ni][r];
                }
            }
        #pragma unroll
        for (int mi = 0; mi < 2; mi++)
            #pragma unroll
            for (int ni = 0; ni < 4; ni++)
                #pragma unroll
                for (int r = 0; r < 4; r++) acc[mi][ni][r] = 0.f;
    };

    // ---- drift pipeline: full barriers (RAW) + empty barriers (WAR), no per-stage syncthreads
    if (tid == 0) { issue(0); issue(1); }
    for (int s = 0; s < 16; s++) {
        mbar_wait(sFull + (s & 1) * 8, (s >> 1) & 1);
        compute(s & 1);
        fold(s);
        mbar_arrive(sEmpty + (s & 1) * 8);
        if (tid == 0 && s + 2 < 16) {
            mbar_wait(sEmpty + (s & 1) * 8, (s >> 1) & 1);
            issue(s + 2);
        }
    }

    // ---- epilogue: write 2x2 output pixels per tile row, scaled by 1/9
    const float inv9 = 1.0f / 9.0f;
    #pragma unroll
    for (int mi = 0; mi < 2; mi++) {
        #pragma unroll
        for (int half = 0; half < 2; half++) {
            const int mrow  = bm * BM2 + wm + mi * 16 + grp + half * 8;
            const int n_img = mrow / TILES;
            const int rr    = mrow - n_img * TILES;
            const int th    = rr / 28;
            const int tw    = rr - th * 28;
            #pragma unroll
            for (int p = 0; p < 2; p++) {
                const int oh = 2 * th + p;
                #pragma unroll
                for (int qq = 0; qq < 2; qq++) {
                    const int ow = 2 * tw + qq;
                    float* orow = out + (size_t)(n_img * HW + oh * WW + ow) * CC
                                + bn * BNc + wn + tig * 2;
                    #pragma unroll
                    for (int ni = 0; ni < 4; ni++) {
                        float2 v;
                        v.x = oacc[p][qq][mi][ni][half * 2 + 0] * inv9;
                        v.y = oacc[p][qq][mi][ni][half * 2 + 1] * inv9;
                        *(float2*)&orow[ni * 8] = v;
                    }
                }
            }
        }
    }
}

// ---------------- launch ----------------
extern "C" void kernel_launch(void* const* d_in, const int* in_sizes, int n_in,
                              void* d_out, int out_size) {
    const float* x = (const float*)d_in[0];
    const float* w = (const float*)d_in[1];
    if (n_in >= 2 && in_sizes[0] == CC * 9 * CC) {
        x = (const float*)d_in[1];
        w = (const float*)d_in[0];
    }
    float* out = (float*)d_out;

    cudaFuncSetAttribute(conv_kernel, cudaFuncAttributeMaxDynamicSharedMemorySize, SMEM_TOTAL);

    wmax_kernel<<<1024, 256>>>(w);
    utrans_kernel<<<256, 256>>>(w);
    vtrans_kernel<<<M2 / 4, 256>>>(x);
    conv_kernel<<<dim3(2, M2 / BM2), 256, SMEM_TOTAL>>>(out);
}